// round 2
// baseline (speedup 1.0000x reference)
#include <cuda_runtime.h>
#include <cuda_bf16.h>

#define N 8192
#define T 256                    // threads per block
#define R 8                      // i's per thread (register-resident)
#define I_PER_BLOCK (T * R)      // 2048
#define I_ROWS (N / I_PER_BLOCK) // 4
#define JC 128                   // number of j-chunks
#define JCHUNK (N / JC)          // 64
#define NB2 (N / T)              // 32 blocks in stage 2

__device__ float g_part[JC * N];   // partial risk sums: [jc][i], 4 MB
__device__ float g_bpart[NB2];     // per-block loss partials (stage 2)
__device__ int   g_count;          // last-block-done counter (zero-init, self-resetting)

// Stage 1: block (irow, jc) computes, for its 2048 i's, the partial
// risk_sum over j in [jc*64, jc*64+64). Each thread holds 8 i's in
// registers; each j is one broadcast LDS.64 amortized over 8 pairs/lane.
__global__ void __launch_bounds__(T, 8)
cox_partial_kernel(const float* __restrict__ hazard,
                   const float* __restrict__ time)
{
    __shared__ float2 te[JCHUNK];            // (time[j], exp(hazard[j]))
    const int tid  = threadIdx.x;
    const int irow = blockIdx.x & (I_ROWS - 1);
    const int jc   = blockIdx.x >> 2;        // I_ROWS == 4

    if (tid < JCHUNK) {
        const int j = jc * JCHUNK + tid;
        te[tid] = make_float2(time[j], expf(hazard[j]));
    }

    const int ibase = irow * I_PER_BLOCK + tid;
    float ti[R], acc[R];
#pragma unroll
    for (int r = 0; r < R; ++r) {
        ti[r]  = time[ibase + r * T];        // coalesced per r
        acc[r] = 0.0f;
    }
    __syncthreads();

#pragma unroll 8
    for (int j = 0; j < JCHUNK; ++j) {
        const float2 v = te[j];              // broadcast, conflict-free
#pragma unroll
        for (int r = 0; r < R; ++r)
            acc[r] += (v.x >= ti[r]) ? v.y : 0.0f;
    }

#pragma unroll
    for (int r = 0; r < R; ++r)
        g_part[jc * N + ibase + r * T] = acc[r];   // coalesced per r
}

// Stage 2: per-i reduction over the 128 j-chunk partials (fixed order ->
// deterministic), per-i loss term, block reduce, then last-block-done
// final reduction over the 32 block partials. No third kernel.
__global__ void __launch_bounds__(T, 8)
cox_finish_kernel(const float* __restrict__ hazard,
                  const float* __restrict__ censor,
                  float* __restrict__ out)
{
    const int tid = threadIdx.x;
    const int i   = blockIdx.x * T + tid;

    float rs = 0.0f;
#pragma unroll 8
    for (int jc = 0; jc < JC; ++jc)
        rs += g_part[jc * N + i];            // coalesced, L2-resident

    float c = (hazard[i] - logf(rs)) * censor[i];

    __shared__ float s[T];
    s[tid] = c;
    __syncthreads();
#pragma unroll
    for (int stride = T / 2; stride >= 32; stride >>= 1) {
        if (tid < stride) s[tid] += s[tid + stride];
        __syncthreads();
    }
    __shared__ int is_last;
    if (tid < 32) {
        float v = s[tid];
#pragma unroll
        for (int o = 16; o > 0; o >>= 1)
            v += __shfl_down_sync(0xffffffffu, v, o);
        if (tid == 0) {
            g_bpart[blockIdx.x] = v;
            __threadfence();
            is_last = (atomicAdd(&g_count, 1) == NB2 - 1);
        }
    }
    __syncthreads();
    if (is_last && tid == 0) {
        float tot = 0.0f;
#pragma unroll
        for (int b = 0; b < NB2; ++b)        // fixed order -> deterministic
            tot += g_bpart[b];
        out[0] = -tot / (float)N;
        g_count = 0;                          // reset for next replay
    }
}

extern "C" void kernel_launch(void* const* d_in, const int* in_sizes, int n_in,
                              void* d_out, int out_size)
{
    const float* hazard = (const float*)d_in[0];
    const float* time_  = (const float*)d_in[1];
    const float* censor = (const float*)d_in[2];
    float* out = (float*)d_out;

    cox_partial_kernel<<<I_ROWS * JC, T>>>(hazard, time_);   // 512 blocks
    cox_finish_kernel<<<NB2, T>>>(hazard, censor, out);      // 32 blocks
}

// round 3
// speedup vs baseline: 1.5895x; 1.5895x over previous
#include <cuda_runtime.h>
#include <cuda_bf16.h>

#define N 8192
#define T 256                    // stage-1 threads per block
#define R 8                      // i's per thread (register tile)
#define I_PER_BLOCK (T * R)      // 2048
#define I_ROWS (N / I_PER_BLOCK) // 4
#define JC 64                    // j-chunks
#define JCHUNK (N / JC)          // 128
#define NB2 (N / 32)             // 256 one-warp blocks in stage 2

__device__ float g_part[JC * N];   // [jc][i] partial risk sums: 2 MB
__device__ float g_bpart[NB2];     // stage-2 per-block loss partials
__device__ int   g_count;          // last-block-done counter (self-resetting)

// Stage 1: block (irow, jc) accumulates, for its 2048 i's, the risk-sum
// contribution of j in [jc*128, jc*128+128). One broadcast LDS.64 per j
// amortized over 8 register-resident i's per lane (~0.066 instr/pair).
__global__ void __launch_bounds__(T, 8)
cox_partial_kernel(const float* __restrict__ hazard,
                   const float* __restrict__ time)
{
    __shared__ float2 te[JCHUNK];
    const int tid  = threadIdx.x;
    const int irow = blockIdx.x & (I_ROWS - 1);
    const int jc   = blockIdx.x >> 2;            // I_ROWS == 4

    if (tid < JCHUNK) {
        const int j = jc * JCHUNK + tid;
        te[tid] = make_float2(time[j], expf(hazard[j]));
    }

    const int ibase = irow * I_PER_BLOCK + tid;
    float ti[R], acc[R];
#pragma unroll
    for (int r = 0; r < R; ++r) {
        ti[r]  = time[ibase + r * T];
        acc[r] = 0.0f;
    }
    __syncthreads();

#pragma unroll 8
    for (int j = 0; j < JCHUNK; ++j) {
        const float2 v = te[j];                  // warp broadcast
#pragma unroll
        for (int r = 0; r < R; ++r)
            if (v.x >= ti[r]) acc[r] += v.y;     // FSETP + @P FADD
    }

#pragma unroll
    for (int r = 0; r < R; ++r)
        g_part[jc * N + ibase + r * T] = acc[r]; // coalesced
}

// Stage 2: 256 one-warp blocks. Each thread reduces its i's 64 chunk
// partials (independent coalesced L2 loads, fixed order), computes the
// per-i loss term, warp-reduces, then last block folds the 256 partials.
__global__ void __launch_bounds__(32, 16)
cox_finish_kernel(const float* __restrict__ hazard,
                  const float* __restrict__ censor,
                  float* __restrict__ out)
{
    const int lane = threadIdx.x;
    const int i    = blockIdx.x * 32 + lane;

    float rs = 0.0f;
#pragma unroll
    for (int jc = 0; jc < JC; ++jc)
        rs += g_part[jc * N + i];                // MLP ~64, L2-resident

    float c = (hazard[i] - logf(rs)) * censor[i];
#pragma unroll
    for (int o = 16; o > 0; o >>= 1)
        c += __shfl_down_sync(0xffffffffu, c, o);

    __shared__ int is_last;
    if (lane == 0) {
        g_bpart[blockIdx.x] = c;
        __threadfence();
        is_last = (atomicAdd(&g_count, 1) == NB2 - 1);
    }
    __syncwarp();

    if (is_last) {
        // lane l sums partials l, l+32, ... (fixed per-lane order), then shfl
        float v = 0.0f;
#pragma unroll
        for (int b = 0; b < NB2 / 32; ++b)
            v += g_bpart[b * 32 + lane];
#pragma unroll
        for (int o = 16; o > 0; o >>= 1)
            v += __shfl_down_sync(0xffffffffu, v, o);
        if (lane == 0) {
            out[0] = -v / (float)N;
            g_count = 0;                         // reset for next replay
        }
    }
}

extern "C" void kernel_launch(void* const* d_in, const int* in_sizes, int n_in,
                              void* d_out, int out_size)
{
    const float* hazard = (const float*)d_in[0];
    const float* time_  = (const float*)d_in[1];
    const float* censor = (const float*)d_in[2];
    float* out = (float*)d_out;

    cox_partial_kernel<<<I_ROWS * JC, T>>>(hazard, time_);   // 256 blocks
    cox_finish_kernel<<<NB2, 32>>>(hazard, censor, out);     // 256 warps
}

// round 4
// speedup vs baseline: 1.6214x; 1.0200x over previous
#include <cuda_runtime.h>
#include <cuda_bf16.h>

#define N 8192
#define T 128                    // stage-1 threads per block
#define R 8                      // i's per thread (register tile)
#define I_PER_BLOCK (T * R)      // 1024
#define I_ROWS (N / I_PER_BLOCK) // 8
#define JC 32                    // j-chunks
#define JCHUNK (N / JC)          // 256
#define NB2 256                  // stage-2 blocks

__device__ float g_part[JC * N];   // [jc][i] partial risk sums: 1 MB
__device__ float g_bpart[NB2];     // stage-2 per-block loss partials
__device__ int   g_count;          // last-block-done counter (self-resetting)

// Stage 1: block (irow, jc) accumulates, for its 1024 i's, the risk-sum
// contribution of j in [jc*256, jc*256+256). One broadcast LDS.64 per j
// amortized over 8 register-resident i's per lane.
__global__ void __launch_bounds__(T, 8)
cox_partial_kernel(const float* __restrict__ hazard,
                   const float* __restrict__ time)
{
    __shared__ float2 te[JCHUNK];
    const int tid  = threadIdx.x;
    const int irow = blockIdx.x & (I_ROWS - 1);
    const int jc   = blockIdx.x >> 3;            // I_ROWS == 8

    for (int t = tid; t < JCHUNK; t += T) {
        const int j = jc * JCHUNK + t;
        te[t] = make_float2(time[j], expf(hazard[j]));
    }

    const int ibase = irow * I_PER_BLOCK + tid;
    float ti[R], acc[R];
#pragma unroll
    for (int r = 0; r < R; ++r) {
        ti[r]  = time[ibase + r * T];
        acc[r] = 0.0f;
    }
    __syncthreads();

#pragma unroll 8
    for (int j = 0; j < JCHUNK; ++j) {
        const float2 v = te[j];                  // warp broadcast
#pragma unroll
        for (int r = 0; r < R; ++r)
            if (v.x >= ti[r]) acc[r] += v.y;     // FSETP + @P FADD
    }

#pragma unroll
    for (int r = 0; r < R; ++r)
        g_part[jc * N + ibase + r * T] = acc[r]; // coalesced
}

// Stage 2: 256 blocks x 256 threads. Block b owns i in [b*32, b*32+32).
// Warp w sums 4 of the 32 jc-partials per i (coalesced 128B loads),
// warps combine in smem, warp 0 computes the per-i loss + block partial;
// the last block folds the 256 block partials.
__global__ void __launch_bounds__(256, 8)
cox_finish_kernel(const float* __restrict__ hazard,
                  const float* __restrict__ censor,
                  float* __restrict__ out)
{
    const int tid  = threadIdx.x;
    const int lane = tid & 31;
    const int w    = tid >> 5;
    const int i    = blockIdx.x * 32 + lane;

    float p = 0.0f;
#pragma unroll
    for (int k = 0; k < 4; ++k)
        p += g_part[(w + 8 * k) * N + i];        // coalesced, MLP=4

    __shared__ float s[256];
    s[w * 32 + lane] = p;
    __syncthreads();

    __shared__ int is_last;
    if (w == 0) {
        float rs = 0.0f;
#pragma unroll
        for (int q = 0; q < 8; ++q)
            rs += s[q * 32 + lane];              // full risk_sum[i]

        float c = (hazard[i] - logf(rs)) * censor[i];
#pragma unroll
        for (int o = 16; o > 0; o >>= 1)
            c += __shfl_down_sync(0xffffffffu, c, o);
        if (lane == 0) {
            g_bpart[blockIdx.x] = c;
            __threadfence();
            is_last = (atomicAdd(&g_count, 1) == NB2 - 1);
        }
    }
    __syncthreads();

    if (is_last && w == 0) {
        float v = 0.0f;
#pragma unroll
        for (int b = 0; b < NB2 / 32; ++b)
            v += g_bpart[b * 32 + lane];         // fixed per-lane order
#pragma unroll
        for (int o = 16; o > 0; o >>= 1)
            v += __shfl_down_sync(0xffffffffu, v, o);
        if (lane == 0) {
            out[0] = -v / (float)N;
            g_count = 0;                         // reset for next replay
        }
    }
}

extern "C" void kernel_launch(void* const* d_in, const int* in_sizes, int n_in,
                              void* d_out, int out_size)
{
    const float* hazard = (const float*)d_in[0];
    const float* time_  = (const float*)d_in[1];
    const float* censor = (const float*)d_in[2];
    float* out = (float*)d_out;

    cox_partial_kernel<<<I_ROWS * JC, T>>>(hazard, time_);   // 256 blocks
    cox_finish_kernel<<<NB2, 256>>>(hazard, censor, out);    // 256 blocks
}